// round 1
// baseline (speedup 1.0000x reference)
#include <cuda_runtime.h>
#include <cstdint>
#include <cstddef>

#define BB   32
#define NAA  32768
#define CC   81
#define NGG  24
#define SENT 0xFFFFFFFFu
#define BPB  37   // blocks per batch for main kernel (37*32 = 1184 blocks = 8/SM)

// ---------------- scratch (device globals; no allocation allowed) ------------
__device__ float              g_ioumax[BB * NAA];
__device__ unsigned char      g_gtidx[BB * NAA];
__device__ unsigned long long g_bestkey[BB * NGG];
__device__ unsigned int       g_negbits[BB * NAA];
__device__ float              g_numpos[BB], g_posce[BB], g_regsum[BB];
__device__ float              g_cls[BB], g_reg[BB], g_np[BB];

// ---------------- init: zero accumulators each replay ------------------------
__global__ void k_init() {
    int t = threadIdx.x;
    if (t < BB) { g_numpos[t] = 0.f; g_posce[t] = 0.f; g_regsum[t] = 0.f; }
    for (int i = t; i < BB * NGG; i += blockDim.x) g_bestkey[i] = 0ull;
}

// ---------------- K1: IoU matching -------------------------------------------
// per anchor: iou_max + argmax over 24 GT (strict > => first-index ties like jnp.argmax)
// per GT: best anchor via monotone key (iou_bits<<32 | (0xFFFFFFFF - a)):
//   higher iou wins; on iou tie, smaller anchor index wins (matches argmax axis=0).
__global__ void __launch_bounds__(256) k_iou(const float* __restrict__ anchors,
                                             const float* __restrict__ gtb) {
    __shared__ float gx0[NGG], gy0[NGG], gx1[NGG], gy1[NGG], garea[NGG];
    __shared__ unsigned long long skey[NGG];
    int b = blockIdx.y;
    int t = threadIdx.x;
    if (t < NGG) {
        float4 g = ((const float4*)gtb)[b * NGG + t];
        float x0 = g.x - 0.5f * g.z, y0 = g.y - 0.5f * g.w;
        float x1 = g.x + 0.5f * g.z, y1 = g.y + 0.5f * g.w;
        gx0[t] = x0; gy0[t] = y0; gx1[t] = x1; gy1[t] = y1;
        garea[t] = (x1 - x0) * (y1 - y0);
        skey[t] = 0ull;
    }
    __syncthreads();

    int a = blockIdx.x * 256 + t;
    float4 an = ((const float4*)anchors)[a];
    float ax0 = an.x - 0.5f * an.z, ay0 = an.y - 0.5f * an.w;
    float ax1 = an.x + 0.5f * an.z, ay1 = an.y + 0.5f * an.w;
    float areaA = (ax1 - ax0) * (ay1 - ay0);

    float best = -1.0f;
    int bg = 0;
    unsigned rkey = 0xFFFFFFFFu - (unsigned)a;

    #pragma unroll 4
    for (int g = 0; g < NGG; ++g) {
        float lx = fmaxf(ax0, gx0[g]), ly = fmaxf(ay0, gy0[g]);
        float rx = fminf(ax1, gx1[g]), ry = fminf(ay1, gy1[g]);
        float w = fmaxf(rx - lx, 0.f), h = fmaxf(ry - ly, 0.f);
        float inter = w * h;
        float uni = fmaxf(areaA + garea[g] - inter, 1e-12f);
        float iou = inter / uni;
        if (iou > best) { best = iou; bg = g; }
        unsigned long long key = ((unsigned long long)__float_as_uint(iou) << 32) | rkey;
        #pragma unroll
        for (int off = 16; off; off >>= 1) {
            unsigned long long o = __shfl_down_sync(0xFFFFFFFFu, key, off);
            if (o > key) key = o;
        }
        if ((t & 31) == 0) atomicMax(&skey[g], key);
    }
    g_ioumax[b * NAA + a] = best;
    g_gtidx[b * NAA + a]  = (unsigned char)bg;
    __syncthreads();
    if (t < NGG) atomicMax(&g_bestkey[b * NGG + t], skey[t]);
}

// ---------------- K2: CE + classification + reg (HBM-bound main kernel) ------
__global__ void __launch_bounds__(256) k_main(const float* __restrict__ cls_pred,
                                              const float* __restrict__ box_pred,
                                              const float* __restrict__ anchors,
                                              const float* __restrict__ gtb,
                                              const int*   __restrict__ gtl) {
    __shared__ int sbest[NGG];
    int b = blockIdx.y;
    int t = threadIdx.x;
    if (t < NGG) {
        unsigned long long k = g_bestkey[b * NGG + t];
        sbest[t] = (int)(0xFFFFFFFFu - (unsigned)(k & 0xFFFFFFFFull));
    }
    __syncthreads();

    int warp = t >> 5, lane = t & 31;
    int wg = blockIdx.x * 8 + warp;           // warp id within batch: 0..BPB*8-1
    float l_np = 0.f, l_ce = 0.f, l_rg = 0.f;

    for (int a = wg; a < NAA; a += BPB * 8) {
        const float* row = cls_pred + ((size_t)(b * NAA + a)) * CC;
        float v0 = row[lane];
        float v1 = row[lane + 32];
        float v2 = (lane < CC - 64) ? row[lane + 64] : -3.0e38f;

        float m = fmaxf(fmaxf(v0, v1), v2);
        #pragma unroll
        for (int off = 16; off; off >>= 1) m = fmaxf(m, __shfl_xor_sync(0xFFFFFFFFu, m, off));
        float s = __expf(v0 - m) + __expf(v1 - m);
        if (lane < CC - 64) s += __expf(v2 - m);
        #pragma unroll
        for (int off = 16; off; off >>= 1) s += __shfl_xor_sync(0xFFFFFFFFu, s, off);
        float lse = m + __logf(s);

        float iom = g_ioumax[b * NAA + a];
        int gi = g_gtidx[b * NAA + a];
        bool pos = (iom >= 0.5f);
        #pragma unroll
        for (int g = 0; g < NGG; ++g) pos = pos || (sbest[g] == a);
        bool ign = (!pos) && (iom > 0.4f);

        int tgt = pos ? gtl[b * NGG + gi] : 0;
        int slot = tgt >> 5, src = tgt & 31;
        float vt = (slot == 0) ? v0 : ((slot == 1) ? v1 : v2);
        vt = __shfl_sync(0xFFFFFFFFu, vt, src);
        float ce = fmaxf(lse - vt, 0.0f);    // ce >= 0 so float bits are order-monotone

        if (lane == 0) {
            if (pos) {
                l_np += 1.f;
                l_ce += ce;
                float4 an = ((const float4*)anchors)[a];
                float4 g  = ((const float4*)gtb)[b * NGG + gi];
                float tx = (g.x - an.x) / an.z / 0.1f;
                float ty = (g.y - an.y) / an.w / 0.1f;
                float tw = __logf(g.z / an.z) / 0.2f;
                float th = __logf(g.w / an.w) / 0.2f;
                float4 bp = ((const float4*)box_pred)[b * NAA + a];
                float d0 = bp.x - tx, d1 = bp.y - ty, d2 = bp.z - tw, d3 = bp.w - th;
                float a0 = fabsf(d0), a1 = fabsf(d1), a2 = fabsf(d2), a3 = fabsf(d3);
                float sl = ((a0 < 1.f) ? 0.5f * d0 * d0 : a0 - 0.5f)
                         + ((a1 < 1.f) ? 0.5f * d1 * d1 : a1 - 0.5f)
                         + ((a2 < 1.f) ? 0.5f * d2 * d2 : a2 - 0.5f)
                         + ((a3 < 1.f) ? 0.5f * d3 * d3 : a3 - 0.5f);
                l_rg += sl;
            }
            g_negbits[b * NAA + a] = (pos || ign) ? SENT : __float_as_uint(ce);
        }
    }
    if (lane == 0) {
        atomicAdd(&g_numpos[b], l_np);
        atomicAdd(&g_posce[b],  l_ce);
        atomicAdd(&g_regsum[b], l_rg);
    }
}

// ---------------- K3: per-batch exact top-K via radix select ------------------
__global__ void __launch_bounds__(1024) k_select() {
    int b = blockIdx.x;
    int t = threadIdx.x;
    const unsigned* vals = g_negbits + b * NAA;
    __shared__ unsigned h[256];
    __shared__ int sk;
    __shared__ unsigned spre;
    __shared__ float ssum;
    __shared__ int scnt;
    __shared__ float res[2];

    // neg count
    int c = 0;
    for (int i = t; i < NAA; i += 1024) c += (vals[i] != SENT);
    #pragma unroll
    for (int off = 16; off; off >>= 1) c += __shfl_xor_sync(0xFFFFFFFFu, c, off);
    if (t == 0) scnt = 0;
    __syncthreads();
    if ((t & 31) == 0) atomicAdd(&scnt, c);
    __syncthreads();
    int negcnt = scnt;

    float np = g_numpos[b];
    int npos = (int)np;
    int Ks[2];
    Ks[0] = min(3 * npos, negcnt);   // hard-negative K
    Ks[1] = min(100, negcnt);        // zero-pos fallback K

    for (int sel = 0; sel < 2; ++sel) {
        int K = Ks[sel];
        float topk = 0.f;
        if (K > 0) {
            if (t == 0) { sk = K; spre = 0; }
            __syncthreads();
            for (int shift = 24; shift >= 0; shift -= 8) {
                for (int i = t; i < 256; i += 1024) h[i] = 0;
                __syncthreads();
                unsigned pre = spre;
                for (int i = t; i < NAA; i += 1024) {
                    unsigned v = vals[i];
                    if (v == SENT) continue;
                    if (shift < 24 && (v >> (shift + 8)) != pre) continue;
                    atomicAdd(&h[(v >> shift) & 255u], 1u);
                }
                __syncthreads();
                if (t == 0) {
                    int k = sk; unsigned d = 0;
                    for (int bin = 255; bin >= 0; --bin) {
                        int hb = (int)h[bin];
                        if (k <= hb) { d = (unsigned)bin; break; }
                        k -= hb;
                    }
                    sk = k;
                    spre = (pre << 8) | d;
                }
                __syncthreads();
            }
            unsigned tv = spre;   // exact bits of the K-th largest neg CE
            float ps = 0.f; int pc = 0;
            for (int i = t; i < NAA; i += 1024) {
                unsigned v = vals[i];
                if (v != SENT && v > tv) { ps += __uint_as_float(v); pc++; }
            }
            #pragma unroll
            for (int off = 16; off; off >>= 1) {
                ps += __shfl_xor_sync(0xFFFFFFFFu, ps, off);
                pc += __shfl_xor_sync(0xFFFFFFFFu, pc, off);
            }
            if (t == 0) { ssum = 0.f; scnt = 0; }
            __syncthreads();
            if ((t & 31) == 0) { atomicAdd(&ssum, ps); atomicAdd(&scnt, pc); }
            __syncthreads();
            topk = ssum + (float)(K - scnt) * __uint_as_float(tv);
        } else {
            __syncthreads();
        }
        if (t == 0) res[sel] = topk;
        __syncthreads();
    }

    if (t == 0) {
        float posce = g_posce[b];
        int K = Ks[0], K0 = Ks[1];
        float cls_pos  = (K > 0) ? (posce + res[0]) / fmaxf(np + (float)K, 1.f)
                                 : posce / fmaxf(np, 1.f);
        float cls_zero = (K0 > 0) ? res[1] / fmaxf((float)K0, 1.f) : 0.f;
        g_cls[b] = (npos > 0) ? cls_pos : cls_zero;
        g_reg[b] = (npos > 0) ? g_regsum[b] / fmaxf(np * 4.f, 1.f) : 0.f;
        g_np[b]  = np;
    }
}

// ---------------- K4: deterministic final reduce ------------------------------
__global__ void k_final(float* __restrict__ out) {
    if (threadIdx.x == 0) {
        float cs = 0.f, rs = 0.f, ns = 0.f;
        for (int b = 0; b < BB; ++b) { cs += g_cls[b]; rs += g_reg[b]; ns += g_np[b]; }
        out[0] = cs / (float)BB;
        out[1] = rs / (float)BB;
        out[2] = ns / (float)BB;
    }
}

// ---------------- launch ------------------------------------------------------
extern "C" void kernel_launch(void* const* d_in, const int* in_sizes, int n_in,
                              void* d_out, int out_size) {
    const float* cls = nullptr;
    const float* box = nullptr;
    const float* anc = nullptr;
    const float* gtb = nullptr;
    const int*   gtl = nullptr;
    for (int i = 0; i < n_in; ++i) {
        long sz = in_sizes[i];
        if      (sz == (long)BB * NAA * CC) cls = (const float*)d_in[i];
        else if (sz == (long)BB * NAA * 4)  box = (const float*)d_in[i];
        else if (sz == (long)NAA * 4)       anc = (const float*)d_in[i];
        else if (sz == (long)BB * NGG * 4)  gtb = (const float*)d_in[i];
        else if (sz == (long)BB * NGG)      gtl = (const int*)d_in[i];
    }
    k_init<<<1, 1024>>>();
    k_iou<<<dim3(NAA / 256, BB), 256>>>(anc, gtb);
    k_main<<<dim3(BPB, BB), 256>>>(cls, box, anc, gtb, gtl);
    k_select<<<BB, 1024>>>();
    k_final<<<1, 32>>>((float*)d_out);
}

// round 2
// speedup vs baseline: 1.4926x; 1.4926x over previous
#include <cuda_runtime.h>
#include <cstdint>
#include <cstddef>

#define BB   32
#define NAA  32768
#define CC   81
#define NGG  24
#define SENT 0xFFFFFFFFu
#define BPB  37            // blocks per batch for k_main
#define WPB  (BPB*8)       // warps per batch = 296

// ---------------- scratch (device globals; no allocation allowed) ------------
__device__ float              g_ioumax[BB * NAA];
__device__ unsigned char      g_gtidx[BB * NAA];
__device__ unsigned long long g_bestkey[BB * NGG];
__device__ unsigned int       g_negbits[BB * NAA];
__device__ unsigned int       g_hist[BB * 1024];      // level-1 hist: ce_bits>>21
__device__ float              g_numpos[BB], g_posce[BB], g_regsum[BB];
__device__ int                g_negcnt[BB];
__device__ float              g_topk[2 * BB];         // [sel*32 + b]

// ---------------- init --------------------------------------------------------
__global__ void k_init() {
    int b = blockIdx.x, t = threadIdx.x;
    for (int i = t; i < 1024; i += 256) g_hist[b * 1024 + i] = 0u;
    if (t == 0) { g_numpos[b] = 0.f; g_posce[b] = 0.f; g_regsum[b] = 0.f; g_negcnt[b] = 0; }
    if (t < NGG) g_bestkey[b * NGG + t] = 0ull;
}

// ---------------- K1: IoU matching (4 anchors/thread) -------------------------
__global__ void __launch_bounds__(256) k_iou(const float* __restrict__ anchors,
                                             const float* __restrict__ gtb) {
    __shared__ float gx0[NGG], gy0[NGG], gx1[NGG], gy1[NGG], garea[NGG];
    __shared__ unsigned long long skey[NGG];
    int b = blockIdx.y, t = threadIdx.x;
    if (t < NGG) {
        float4 g = ((const float4*)gtb)[b * NGG + t];
        float x0 = g.x - 0.5f * g.z, y0 = g.y - 0.5f * g.w;
        float x1 = g.x + 0.5f * g.z, y1 = g.y + 0.5f * g.w;
        gx0[t] = x0; gy0[t] = y0; gx1[t] = x1; gy1[t] = y1;
        garea[t] = (x1 - x0) * (y1 - y0);
        skey[t] = 0ull;
    }
    __syncthreads();

    int abase = blockIdx.x * 1024 + t;     // 4 anchors: abase + k*256
    float ax0[4], ay0[4], ax1[4], ay1[4], areaA[4];
    #pragma unroll
    for (int k = 0; k < 4; ++k) {
        float4 an = ((const float4*)anchors)[abase + k * 256];
        ax0[k] = an.x - 0.5f * an.z; ay0[k] = an.y - 0.5f * an.w;
        ax1[k] = an.x + 0.5f * an.z; ay1[k] = an.y + 0.5f * an.w;
        areaA[k] = (ax1[k] - ax0[k]) * (ay1[k] - ay0[k]);
    }
    float best[4] = {-1.f, -1.f, -1.f, -1.f};
    int   bg[4]   = {0, 0, 0, 0};

    for (int g = 0; g < NGG; ++g) {
        unsigned long long key = 0ull;
        #pragma unroll
        for (int k = 0; k < 4; ++k) {
            float lx = fmaxf(ax0[k], gx0[g]), ly = fmaxf(ay0[k], gy0[g]);
            float rx = fminf(ax1[k], gx1[g]), ry = fminf(ay1[k], gy1[g]);
            float w = fmaxf(rx - lx, 0.f), h = fmaxf(ry - ly, 0.f);
            float inter = w * h;
            float uni = fmaxf(areaA[k] + garea[g] - inter, 1e-12f);
            float iou = inter / uni;
            if (iou > best[k]) { best[k] = iou; bg[k] = g; }
            unsigned long long kk = ((unsigned long long)__float_as_uint(iou) << 32)
                                  | (0xFFFFFFFFu - (unsigned)(abase + k * 256));
            if (kk > key) key = kk;
        }
        #pragma unroll
        for (int off = 16; off; off >>= 1) {
            unsigned long long o = __shfl_down_sync(0xFFFFFFFFu, key, off);
            if (o > key) key = o;
        }
        if ((t & 31) == 0) atomicMax(&skey[g], key);
    }
    #pragma unroll
    for (int k = 0; k < 4; ++k) {
        g_ioumax[b * NAA + abase + k * 256] = best[k];
        g_gtidx[b * NAA + abase + k * 256]  = (unsigned char)bg[k];
    }
    __syncthreads();
    if (t < NGG) atomicMax(&g_bestkey[b * NGG + t], skey[t]);
}

// ---------------- K2: CE + classify + reg + neg hist (HBM-bound) --------------
__global__ void __launch_bounds__(256) k_main(const float* __restrict__ cls_pred,
                                              const float* __restrict__ box_pred,
                                              const float* __restrict__ anchors,
                                              const float* __restrict__ gtb,
                                              const int*   __restrict__ gtl) {
    __shared__ unsigned bm[1024];     // bitmap of per-GT best anchors
    __shared__ int    slab[NGG];
    __shared__ float4 sgt[NGG];
    int b = blockIdx.y, t = threadIdx.x;
    for (int i = t; i < 1024; i += 256) bm[i] = 0u;
    if (t < NGG) {
        slab[t] = gtl[b * NGG + t];
        sgt[t]  = ((const float4*)gtb)[b * NGG + t];
    }
    __syncthreads();
    if (t < NGG) {
        unsigned a = 0xFFFFFFFFu - (unsigned)(g_bestkey[b * NGG + t] & 0xFFFFFFFFull);
        atomicOr(&bm[a >> 5], 1u << (a & 31));
    }
    __syncthreads();

    int warp = t >> 5, lane = t & 31;
    int wg = blockIdx.x * 8 + warp;
    float l_np = 0.f, l_ce = 0.f, l_rg = 0.f;
    int   l_ng = 0;
    const float* base = cls_pred + (size_t)b * NAA * CC;

    for (int p = wg; p < NAA / 2; p += WPB) {
        int a0 = 2 * p, a1 = a0 + 1;
        const float* r0 = base + (size_t)a0 * CC;
        const float* r1 = r0 + CC;
        float v00 = r0[lane], v01 = r0[lane + 32];
        float v10 = r1[lane], v11 = r1[lane + 32];
        float v02 = 0.f, v12 = 0.f;
        if (lane < CC - 64) { v02 = r0[lane + 64]; v12 = r1[lane + 64]; }

        float s0 = __expf(v00) + __expf(v01);
        float s1 = __expf(v10) + __expf(v11);
        if (lane < CC - 64) { s0 += __expf(v02); s1 += __expf(v12); }
        #pragma unroll
        for (int off = 16; off; off >>= 1) {
            s0 += __shfl_xor_sync(0xFFFFFFFFu, s0, off);
            s1 += __shfl_xor_sync(0xFFFFFFFFu, s1, off);
        }
        float lse0 = __logf(s0), lse1 = __logf(s1);

        float io0 = g_ioumax[b * NAA + a0], io1 = g_ioumax[b * NAA + a1];
        int   gi0 = g_gtidx[b * NAA + a0],  gi1 = g_gtidx[b * NAA + a1];
        bool pos0 = (io0 >= 0.5f) || ((bm[a0 >> 5] >> (a0 & 31)) & 1u);
        bool pos1 = (io1 >= 0.5f) || ((bm[a1 >> 5] >> (a1 & 31)) & 1u);
        bool ign0 = !pos0 && (io0 > 0.4f);
        bool ign1 = !pos1 && (io1 > 0.4f);

        int tg0 = pos0 ? slab[gi0] : 0;
        int tg1 = pos1 ? slab[gi1] : 0;
        int sl0 = tg0 >> 5, sl1 = tg1 >> 5;
        float w0 = (sl0 == 0) ? v00 : ((sl0 == 1) ? v01 : v02);
        float w1 = (sl1 == 0) ? v10 : ((sl1 == 1) ? v11 : v12);
        float vt0 = __shfl_sync(0xFFFFFFFFu, w0, tg0 & 31);
        float vt1 = __shfl_sync(0xFFFFFFFFu, w1, tg1 & 31);
        float ce0 = fmaxf(lse0 - vt0, 0.f);
        float ce1 = fmaxf(lse1 - vt1, 0.f);

        if (lane < 2) {
            int   a   = lane ? a1  : a0;
            bool  pos = lane ? pos1 : pos0;
            bool  ign = lane ? ign1 : ign0;
            float ce  = lane ? ce1 : ce0;
            int   gi  = lane ? gi1 : gi0;
            if (pos) {
                l_np += 1.f; l_ce += ce;
                float4 an = ((const float4*)anchors)[a];
                float4 g  = sgt[gi];
                float tx = (g.x - an.x) / an.z / 0.1f;
                float ty = (g.y - an.y) / an.w / 0.1f;
                float tw = __logf(g.z / an.z) / 0.2f;
                float th = __logf(g.w / an.w) / 0.2f;
                float4 bp = ((const float4*)box_pred)[b * NAA + a];
                float d0 = bp.x - tx, d1 = bp.y - ty, d2 = bp.z - tw, d3 = bp.w - th;
                float e0 = fabsf(d0), e1 = fabsf(d1), e2 = fabsf(d2), e3 = fabsf(d3);
                l_rg += ((e0 < 1.f) ? 0.5f * d0 * d0 : e0 - 0.5f)
                      + ((e1 < 1.f) ? 0.5f * d1 * d1 : e1 - 0.5f)
                      + ((e2 < 1.f) ? 0.5f * d2 * d2 : e2 - 0.5f)
                      + ((e3 < 1.f) ? 0.5f * d3 * d3 : e3 - 0.5f);
            }
            bool neg = !pos && !ign;
            unsigned bits = neg ? __float_as_uint(ce) : SENT;
            g_negbits[b * NAA + a] = bits;
            if (neg) {
                ++l_ng;
                atomicAdd(&g_hist[b * 1024 + (bits >> 21)], 1u);
            }
        }
    }
    // fold lanes 0/1 into lane 0 and push
    #pragma unroll
    for (int off = 1; off < 2; off <<= 1) {
        l_np += __shfl_down_sync(0xFFFFFFFFu, l_np, off);
        l_ce += __shfl_down_sync(0xFFFFFFFFu, l_ce, off);
        l_rg += __shfl_down_sync(0xFFFFFFFFu, l_rg, off);
        l_ng += __shfl_down_sync(0xFFFFFFFFu, l_ng, off);
    }
    if (lane == 0) {
        atomicAdd(&g_numpos[b], l_np);
        atomicAdd(&g_posce[b],  l_ce);
        atomicAdd(&g_regsum[b], l_rg);
        atomicAdd(&g_negcnt[b], l_ng);
    }
}

// ---------------- k_select helpers --------------------------------------------
// warp0 finds bin t with suffix_above < K <= suffix_above + cnt[t]; sh[0]=t, sh[1]=K-suffix_above
__device__ __forceinline__ void select_bin(const unsigned* cnt, int NB, int K, int* sh) {
    int t = threadIdx.x;
    if (t < 32) {
        int chunk = NB / 32;
        int base = NB - 1 - t * chunk;     // lane's highest bin
        int csum = 0;
        for (int j = 0; j < chunk; ++j) csum += (int)cnt[base - j];
        int incl = csum;
        #pragma unroll
        for (int off = 1; off < 32; off <<= 1) {
            int o = __shfl_up_sync(0xFFFFFFFFu, incl, off);
            if (t >= off) incl += o;
        }
        int excl = incl - csum;
        if (excl < K && K <= incl) {
            int running = excl;
            for (int j = 0; j < chunk; ++j) {
                int c = (int)cnt[base - j];
                if (running + c >= K) { sh[0] = base - j; sh[1] = K - running; break; }
                running += c;
            }
        }
    }
}

__device__ __forceinline__ float block_sum(float v, float* sred) {
    int lane = threadIdx.x & 31, w = threadIdx.x >> 5;
    #pragma unroll
    for (int off = 16; off; off >>= 1) v += __shfl_xor_sync(0xFFFFFFFFu, v, off);
    __syncthreads();
    if (lane == 0) sred[w] = v;
    __syncthreads();
    if (threadIdx.x < 32) {
        float r = sred[threadIdx.x];
        #pragma unroll
        for (int off = 16; off; off >>= 1) r += __shfl_xor_sync(0xFFFFFFFFu, r, off);
        if (threadIdx.x == 0) sred[0] = r;
    }
    __syncthreads();
    return sred[0];
}

// ---------------- K3: exact top-K via 3-level hist select (2 array passes) ----
__global__ void __launch_bounds__(1024) k_select() {
    int b = blockIdx.x & 31;
    int sel = blockIdx.x >> 5;
    int t = threadIdx.x;
    __shared__ unsigned cnt2[2048];
    __shared__ float    fsum2[2048];
    __shared__ int      sh[2];
    __shared__ float    sred[32];
    const unsigned* vals = g_negbits + b * NAA;

    int   neg  = g_negcnt[b];
    float np   = g_numpos[b];
    int   npos = (int)np;
    int   K    = sel ? min(100, neg) : min(3 * npos, neg);
    if (K <= 0) { if (t == 0) g_topk[blockIdx.x] = 0.f; return; }

    // level 1: global 1024-bin hist (bits >> 21; sign always 0 for ce >= 0)
    select_bin(g_hist + b * 1024, 1024, K, sh);
    __syncthreads();
    int t1 = sh[0], k1 = sh[1];

    // pass A: sum above t1; build 11-bit sub-hist (+value sums) within t1
    for (int i = t; i < 2048; i += 1024) { cnt2[i] = 0u; fsum2[i] = 0.f; }
    __syncthreads();
    float ps = 0.f;
    for (int i = t; i < NAA; i += 1024) {
        unsigned v = vals[i];
        if (v == SENT) continue;
        int b1 = (int)(v >> 21);
        if (b1 > t1) ps += __uint_as_float(v);
        else if (b1 == t1) {
            unsigned sb = (v >> 10) & 0x7FFu;
            atomicAdd(&cnt2[sb], 1u);
            atomicAdd(&fsum2[sb], __uint_as_float(v));
        }
    }
    float S1 = block_sum(ps, sred);

    // level 2
    select_bin(cnt2, 2048, k1, sh);
    __syncthreads();
    int t2 = sh[0], k2 = sh[1];
    float s2 = 0.f;
    for (int i = t; i < 2048; i += 1024) if (i > t2) s2 += fsum2[i];
    float S2 = block_sum(s2, sred);

    // pass B: exact low 10 bits within (t1,t2)
    __syncthreads();
    for (int i = t; i < 1024; i += 1024) { cnt2[i] = 0u; fsum2[i] = 0.f; }
    __syncthreads();
    unsigned hi22 = ((unsigned)t1 << 11) | (unsigned)t2;
    for (int i = t; i < NAA; i += 1024) {
        unsigned v = vals[i];
        if (v == SENT) continue;
        if ((v >> 10) == hi22) {
            atomicAdd(&cnt2[v & 0x3FFu], 1u);
            atomicAdd(&fsum2[v & 0x3FFu], __uint_as_float(v));
        }
    }
    __syncthreads();
    select_bin(cnt2, 1024, k2, sh);
    __syncthreads();
    int t3 = sh[0], k3 = sh[1];
    float s3 = 0.f;
    for (int i = t; i < 1024; i += 1024) if (i > t3) s3 += fsum2[i];
    float S3 = block_sum(s3, sred);

    if (t == 0) {
        unsigned tv = ((unsigned)t1 << 21) | ((unsigned)t2 << 10) | (unsigned)t3;
        g_topk[blockIdx.x] = S1 + S2 + S3 + (float)k3 * __uint_as_float(tv);
    }
}

// ---------------- K4: deterministic final reduce ------------------------------
__global__ void k_final(float* __restrict__ out) {
    if (threadIdx.x == 0) {
        float cs = 0.f, rs = 0.f, ns = 0.f;
        for (int b = 0; b < BB; ++b) {
            float np = g_numpos[b];
            int npos = (int)np;
            int neg = g_negcnt[b];
            int K  = min(3 * npos, neg);
            int K0 = min(100, neg);
            float cls_pos  = (K > 0) ? (g_posce[b] + g_topk[b]) / fmaxf(np + (float)K, 1.f)
                                     : g_posce[b] / fmaxf(np, 1.f);
            float cls_zero = (K0 > 0) ? g_topk[32 + b] / fmaxf((float)K0, 1.f) : 0.f;
            cs += (npos > 0) ? cls_pos : cls_zero;
            rs += (npos > 0) ? g_regsum[b] / fmaxf(np * 4.f, 1.f) : 0.f;
            ns += np;
        }
        out[0] = cs / (float)BB;
        out[1] = rs / (float)BB;
        out[2] = ns / (float)BB;
    }
}

// ---------------- launch ------------------------------------------------------
extern "C" void kernel_launch(void* const* d_in, const int* in_sizes, int n_in,
                              void* d_out, int out_size) {
    const float* cls = nullptr;
    const float* box = nullptr;
    const float* anc = nullptr;
    const float* gtb = nullptr;
    const int*   gtl = nullptr;
    for (int i = 0; i < n_in; ++i) {
        long sz = in_sizes[i];
        if      (sz == (long)BB * NAA * CC) cls = (const float*)d_in[i];
        else if (sz == (long)BB * NAA * 4)  box = (const float*)d_in[i];
        else if (sz == (long)NAA * 4)       anc = (const float*)d_in[i];
        else if (sz == (long)BB * NGG * 4)  gtb = (const float*)d_in[i];
        else if (sz == (long)BB * NGG)      gtl = (const int*)d_in[i];
    }
    k_init<<<BB, 256>>>();
    k_iou<<<dim3(NAA / 1024, BB), 256>>>(anc, gtb);
    k_main<<<dim3(BPB, BB), 256>>>(cls, box, anc, gtb, gtl);
    k_select<<<64, 1024>>>();
    k_final<<<1, 32>>>((float*)d_out);
}

// round 3
// speedup vs baseline: 1.6192x; 1.0849x over previous
#include <cuda_runtime.h>
#include <cuda_pipeline.h>
#include <cstdint>
#include <cstddef>

#define BB   32
#define NAA  32768
#define CC   81
#define NGG  24
#define SENT 0xFFFFFFFFu
#define NBIN 16384
#define TILE 256
#define NTILES ((BB*NAA)/TILE)      // 4096
#define TILE_F4 ((TILE*CC)/4)       // 5184
#define CAP  6144

// ---------------- scratch ------------------------------------------------------
__device__ float              g_ioumax[BB*NAA];
__device__ unsigned char      g_gtidx[BB*NAA];
__device__ unsigned long long g_bestkey[BB*NGG];
__device__ unsigned           g_negbits[BB*NAA];
__device__ unsigned           g_hcnt[BB*NBIN];
__device__ float              g_hsum[BB*NBIN];
__device__ float              g_numpos[BB], g_posce[BB], g_regsum[BB];
__device__ float              g_topk[2*BB];
__device__ int                g_K[2*BB];
__device__ int                g_ctr;

__device__ __forceinline__ unsigned redux_max(unsigned v){
    unsigned r; asm("redux.sync.max.u32 %0, %1, 0xffffffff;" : "=r"(r) : "r"(v)); return r;
}

// ---------------- init ---------------------------------------------------------
__global__ void k_init(){
    int i = blockIdx.x*256 + threadIdx.x;
    for (int j=i; j<BB*NBIN; j+=gridDim.x*256){ g_hcnt[j]=0u; g_hsum[j]=0.f; }
    if (i < BB*NGG) g_bestkey[i]=0ull;
    if (i < BB){ g_numpos[i]=0.f; g_posce[i]=0.f; g_regsum[i]=0.f; }
    if (i==0) g_ctr = 0;
}

// ---------------- K1: IoU matching (4 anchors/thread, REDUX per-GT) ------------
__global__ void __launch_bounds__(256) k_iou(const float* __restrict__ anchors,
                                             const float* __restrict__ gtb){
    __shared__ float gx0[NGG],gy0[NGG],gx1[NGG],gy1[NGG],garea[NGG];
    __shared__ unsigned long long skey[NGG];
    int b=blockIdx.y, t=threadIdx.x;
    if (t<NGG){
        float4 g=((const float4*)gtb)[b*NGG+t];
        float x0=g.x-0.5f*g.z, y0=g.y-0.5f*g.w, x1=g.x+0.5f*g.z, y1=g.y+0.5f*g.w;
        gx0[t]=x0; gy0[t]=y0; gx1[t]=x1; gy1[t]=y1; garea[t]=(x1-x0)*(y1-y0);
        skey[t]=0ull;
    }
    __syncthreads();
    int abase = blockIdx.x*1024 + t;
    float ax0[4],ay0[4],ax1[4],ay1[4],areaA[4];
    #pragma unroll
    for (int k=0;k<4;++k){
        float4 an=((const float4*)anchors)[abase+k*256];
        ax0[k]=an.x-0.5f*an.z; ay0[k]=an.y-0.5f*an.w;
        ax1[k]=an.x+0.5f*an.z; ay1[k]=an.y+0.5f*an.w;
        areaA[k]=(ax1[k]-ax0[k])*(ay1[k]-ay0[k]);
    }
    float best[4]={-1.f,-1.f,-1.f,-1.f}; int bg[4]={0,0,0,0};

    for (int g=0; g<NGG; ++g){
        float bi=-1.f; int bk=0;
        #pragma unroll
        for (int k=0;k<4;++k){
            float lx=fmaxf(ax0[k],gx0[g]), ly=fmaxf(ay0[k],gy0[g]);
            float rx=fminf(ax1[k],gx1[g]), ry=fminf(ay1[k],gy1[g]);
            float w=fmaxf(rx-lx,0.f), h=fmaxf(ry-ly,0.f);
            float inter=w*h;
            float uni=fmaxf(areaA[k]+garea[g]-inter, 1e-12f);
            float iou=inter/uni;
            if (iou>best[k]){best[k]=iou; bg[k]=g;}
            if (iou>bi){bi=iou; bk=k;}
        }
        unsigned mb=__float_as_uint(bi);
        unsigned M=redux_max(mb);
        unsigned rk=(mb==M)? (unsigned)(((3-bk)<<5)|(31-(t&31)))+1u : 0u;
        unsigned R=redux_max(rk);
        if ((t&31)==0){
            int wl=31-(int)((R-1u)&31u), wk=3-(int)((R-1u)>>5);
            unsigned a=(unsigned)(blockIdx.x*1024 + (t&~31) + wl + wk*256);
            atomicMax(&skey[g], ((unsigned long long)M<<32) | (0xFFFFFFFFu - a));
        }
    }
    #pragma unroll
    for (int k=0;k<4;++k){
        g_ioumax[b*NAA+abase+k*256]=best[k];
        g_gtidx[b*NAA+abase+k*256]=(unsigned char)bg[k];
    }
    __syncthreads();
    if (t<NGG) atomicMax(&g_bestkey[b*NGG+t], skey[t]);
}

// ---------------- K1b: mark forced positives (iou := 2.0) ----------------------
__global__ void k_force(){
    int i = threadIdx.x;
    if (i < BB*NGG){
        unsigned a = 0xFFFFFFFFu - (unsigned)(g_bestkey[i] & 0xFFFFFFFFull);
        int b = i / NGG;
        g_ioumax[(size_t)b*NAA + a] = 2.0f;
    }
}

// ---------------- K2: CE + classify + reg, smem-staged, shuffle-free -----------
__global__ void __launch_bounds__(256) k_main(const float* __restrict__ cls,
                                              const float* __restrict__ box,
                                              const float* __restrict__ anchors,
                                              const float* __restrict__ gtb,
                                              const int*   __restrict__ gtl){
    extern __shared__ float sbuf[];
    const int t = threadIdx.x;
    float* bufs[2] = { sbuf, sbuf + TILE*CC };
    __shared__ int s_tile;

    if (t==0) s_tile = atomicAdd(&g_ctr, 1);
    __syncthreads();
    int cur = s_tile;
    if (cur >= NTILES) return;
    {   // prologue load
        const float4* src=(const float4*)(cls + (size_t)cur*TILE*CC);
        float4* dst=(float4*)bufs[0];
        for (int i=t;i<TILE_F4;i+=256) __pipeline_memcpy_async(dst+i, src+i, 16);
        __pipeline_commit();
    }
    int idx = 0;
    for(;;){
        __syncthreads();                   // readers of s_tile / prev buffer done
        if (t==0) s_tile = atomicAdd(&g_ctr, 1);
        __syncthreads();
        int nxt = s_tile;
        if (nxt < NTILES){
            const float4* src=(const float4*)(cls + (size_t)nxt*TILE*CC);
            float4* dst=(float4*)bufs[idx^1];
            for (int i=t;i<TILE_F4;i+=256) __pipeline_memcpy_async(dst+i, src+i, 16);
            __pipeline_commit();
            __pipeline_wait_prior(1);
        } else {
            __pipeline_wait_prior(0);
        }
        __syncthreads();                   // current tile fully staged

        int row = cur*TILE + t;
        int b   = row >> 15;
        int a   = row & (NAA-1);
        float io = g_ioumax[row];
        int   gi = (int)g_gtidx[row];
        const float* r = bufs[idx] + t*CC;

        float s0=0.f,s1=0.f,s2=0.f,s3=0.f;
        #pragma unroll
        for (int c=0;c<80;c+=4){
            s0+=__expf(r[c]); s1+=__expf(r[c+1]); s2+=__expf(r[c+2]); s3+=__expf(r[c+3]);
        }
        float lse = __logf((s0+s1)+(s2+s3)+__expf(r[80]));

        bool pos = io >= 0.5f;             // forced positives carry io=2.0
        bool ign = (!pos) && (io > 0.4f);
        float l_np=0.f, l_ce=0.f, l_rg=0.f;

        if (pos){
            int tgt = gtl[b*NGG + gi];
            float ce = fmaxf(lse - r[tgt], 0.f);
            l_np = 1.f; l_ce = ce;
            float4 an = ((const float4*)anchors)[a];
            float4 g  = ((const float4*)gtb)[b*NGG + gi];
            float tx = (g.x - an.x) / an.z / 0.1f;
            float ty = (g.y - an.y) / an.w / 0.1f;
            float tw = __logf(g.z / an.z) / 0.2f;
            float th = __logf(g.w / an.w) / 0.2f;
            float4 bp = ((const float4*)box)[(size_t)b*NAA + a];
            float d0=bp.x-tx, d1=bp.y-ty, d2=bp.z-tw, d3=bp.w-th;
            float e0=fabsf(d0), e1=fabsf(d1), e2=fabsf(d2), e3=fabsf(d3);
            l_rg = ((e0<1.f)?0.5f*d0*d0:e0-0.5f) + ((e1<1.f)?0.5f*d1*d1:e1-0.5f)
                 + ((e2<1.f)?0.5f*d2*d2:e2-0.5f) + ((e3<1.f)?0.5f*d3*d3:e3-0.5f);
            g_negbits[row] = SENT;
        } else if (ign){
            g_negbits[row] = SENT;
        } else {
            float ce = fmaxf(lse - r[0], 0.f);
            unsigned bits = __float_as_uint(ce);
            g_negbits[row] = bits;
            atomicAdd(&g_hcnt[b*NBIN + (bits>>18)], 1u);
            atomicAdd(&g_hsum[b*NBIN + (bits>>18)], ce);
        }
        #pragma unroll
        for (int off=16;off;off>>=1){
            l_np += __shfl_xor_sync(0xFFFFFFFFu, l_np, off);
            l_ce += __shfl_xor_sync(0xFFFFFFFFu, l_ce, off);
            l_rg += __shfl_xor_sync(0xFFFFFFFFu, l_rg, off);
        }
        if ((t&31)==0 && l_np > 0.f){
            atomicAdd(&g_numpos[b], l_np);
            atomicAdd(&g_posce[b],  l_ce);
            atomicAdd(&g_regsum[b], l_rg);
        }
        if (nxt >= NTILES) break;
        cur = nxt; idx ^= 1;
    }
}

// ---------------- warp-scale select over 512 smem bins -------------------------
__device__ void warp_select(const unsigned* cnt, const float* fs, int K,
                            int* o_bin, int* o_k, float* o_S){
    int l = threadIdx.x;               // caller guarantees l < 32
    int base = l*16;
    unsigned c=0; float f=0.f;
    #pragma unroll
    for (int j=0;j<16;++j){ c+=cnt[base+j]; f+=fs[base+j]; }
    unsigned ci=c; float fi=f;
    #pragma unroll
    for (int off=1;off<32;off<<=1){
        unsigned uc=__shfl_up_sync(0xFFFFFFFFu,ci,off);
        float    uf=__shfl_up_sync(0xFFFFFFFFu,fi,off);
        if (l>=off){ ci+=uc; fi+=uf; }
    }
    unsigned total=__shfl_sync(0xFFFFFFFFu,ci,31);
    float    ftot =__shfl_sync(0xFFFFFFFFu,fi,31);
    unsigned SA=total-ci; float FA=ftot-fi;
    if (SA < (unsigned)K && (unsigned)K <= SA + c){
        unsigned run=SA; float fab=FA;
        for (int j=15;j>=0;--j){
            unsigned cb=cnt[base+j];
            if (run + cb >= (unsigned)K){ *o_bin=base+j; *o_k=(int)((unsigned)K-run); *o_S=fab; break; }
            run += cb; fab += fs[base+j];
        }
    }
}

// ---------------- K3: exact top-K, ~1 global pass ------------------------------
__global__ void __launch_bounds__(1024) k_select(){
    int b=blockIdx.x&31, sel=blockIdx.x>>5, t=threadIdx.x;
    int lane=t&31, warp=t>>5;
    const unsigned* cnt=g_hcnt + b*NBIN;
    const float*    fsm=g_hsum + b*NBIN;
    __shared__ unsigned swc[32]; __shared__ float swf[32];
    __shared__ int s_t1, s_k1;  __shared__ float s_S1;
    __shared__ int s_bin, s_k;  __shared__ float s_S;
    __shared__ int s_n;
    __shared__ unsigned cnt2[512]; __shared__ float fs2[512];
    __shared__ unsigned slist[CAP];

    int base=t*16;
    unsigned c=0; float f=0.f;
    #pragma unroll
    for (int j=0;j<16;++j){ c+=cnt[base+j]; f+=fsm[base+j]; }
    unsigned ci=c; float fi=f;
    #pragma unroll
    for (int off=1;off<32;off<<=1){
        unsigned uc=__shfl_up_sync(0xFFFFFFFFu,ci,off);
        float    uf=__shfl_up_sync(0xFFFFFFFFu,fi,off);
        if (lane>=off){ ci+=uc; fi+=uf; }
    }
    if (lane==31){ swc[warp]=ci; swf[warp]=fi; }
    __syncthreads();
    if (t<32){
        unsigned u=swc[t]; float g=swf[t];
        #pragma unroll
        for (int off=1;off<32;off<<=1){
            unsigned uu=__shfl_up_sync(0xFFFFFFFFu,u,off);
            float    gg=__shfl_up_sync(0xFFFFFFFFu,g,off);
            if (t>=off){ u+=uu; g+=gg; }
        }
        swc[t]=u; swf[t]=g;
    }
    __syncthreads();
    unsigned P = ci + (warp ? swc[warp-1] : 0u);
    float    FP= fi + (warp ? swf[warp-1] : 0.f);
    unsigned total=swc[31]; float ftot=swf[31];

    float np = g_numpos[b];
    int negcnt = (int)total;
    int K = sel ? min(100, negcnt) : min(3*(int)np, negcnt);
    if (t==0) g_K[blockIdx.x] = K;
    if (K<=0){ if (t==0) g_topk[blockIdx.x]=0.f; return; }

    unsigned SA = total - P; float FA = ftot - FP;
    if (SA < (unsigned)K && (unsigned)K <= SA + c){
        unsigned run=SA; float fab=FA;
        for (int j=15;j>=0;--j){
            unsigned cb=cnt[base+j];
            if (run + cb >= (unsigned)K){ s_t1=base+j; s_k1=(int)((unsigned)K-run); s_S1=fab; break; }
            run += cb; fab += fsm[base+j];
        }
    }
    if (t==0) s_n=0;
    for (int i=t;i<512;i+=1024){ cnt2[i]=0u; fs2[i]=0.f; }
    __syncthreads();
    int t1=s_t1, k1=s_k1; float S1=s_S1;
    unsigned cT1 = cnt[t1];
    const unsigned* vals = g_negbits + b*NAA;
    bool collect = (cT1 <= CAP);
    if (collect){
        for (int i=t;i<NAA;i+=1024){
            unsigned v=vals[i];
            if ((v>>18)==(unsigned)t1){ int p=atomicAdd(&s_n,1); slist[p]=v; }
        }
    }
    __syncthreads();
    int n=s_n;
    if (collect){
        for (int i=t;i<n;i+=1024){
            unsigned v=slist[i];
            atomicAdd(&cnt2[(v>>9)&511u],1u); atomicAdd(&fs2[(v>>9)&511u],__uint_as_float(v));
        }
    } else {
        for (int i=t;i<NAA;i+=1024){
            unsigned v=vals[i];
            if ((v>>18)==(unsigned)t1){ atomicAdd(&cnt2[(v>>9)&511u],1u); atomicAdd(&fs2[(v>>9)&511u],__uint_as_float(v)); }
        }
    }
    __syncthreads();
    if (t<32) warp_select(cnt2, fs2, k1, &s_bin, &s_k, &s_S);
    __syncthreads();
    int t2=s_bin, k2=s_k; float S2=s_S;
    for (int i=t;i<512;i+=1024){ cnt2[i]=0u; fs2[i]=0.f; }
    __syncthreads();
    unsigned pfx = ((unsigned)t1<<9) | (unsigned)t2;
    if (collect){
        for (int i=t;i<n;i+=1024){
            unsigned v=slist[i];
            if ((v>>9)==pfx){ atomicAdd(&cnt2[v&511u],1u); atomicAdd(&fs2[v&511u],__uint_as_float(v)); }
        }
    } else {
        for (int i=t;i<NAA;i+=1024){
            unsigned v=vals[i];
            if ((v>>9)==pfx){ atomicAdd(&cnt2[v&511u],1u); atomicAdd(&fs2[v&511u],__uint_as_float(v)); }
        }
    }
    __syncthreads();
    if (t<32) warp_select(cnt2, fs2, k2, &s_bin, &s_k, &s_S);
    __syncthreads();
    if (t==0){
        unsigned tv = (pfx<<9) | (unsigned)s_bin;
        g_topk[blockIdx.x] = S1 + S2 + s_S + (float)s_k * __uint_as_float(tv);
    }
}

// ---------------- K4: deterministic final reduce -------------------------------
__global__ void k_final(float* __restrict__ out){
    if (threadIdx.x==0){
        float cs=0.f, rs=0.f, ns=0.f;
        for (int b=0;b<BB;++b){
            float np=g_numpos[b]; int npos=(int)np;
            int K=g_K[b], K0=g_K[32+b];
            float cls_pos  = (K>0)  ? (g_posce[b]+g_topk[b]) / fmaxf(np+(float)K,1.f)
                                    : g_posce[b] / fmaxf(np,1.f);
            float cls_zero = (K0>0) ? g_topk[32+b] / fmaxf((float)K0,1.f) : 0.f;
            cs += (npos>0) ? cls_pos : cls_zero;
            rs += (npos>0) ? g_regsum[b] / fmaxf(np*4.f,1.f) : 0.f;
            ns += np;
        }
        out[0]=cs/(float)BB; out[1]=rs/(float)BB; out[2]=ns/(float)BB;
    }
}

// ---------------- launch -------------------------------------------------------
extern "C" void kernel_launch(void* const* d_in, const int* in_sizes, int n_in,
                              void* d_out, int out_size) {
    const float* cls=nullptr; const float* box=nullptr; const float* anc=nullptr;
    const float* gtb=nullptr; const int* gtl=nullptr;
    for (int i=0;i<n_in;++i){
        long sz=in_sizes[i];
        if      (sz==(long)BB*NAA*CC) cls=(const float*)d_in[i];
        else if (sz==(long)BB*NAA*4)  box=(const float*)d_in[i];
        else if (sz==(long)NAA*4)     anc=(const float*)d_in[i];
        else if (sz==(long)BB*NGG*4)  gtb=(const float*)d_in[i];
        else if (sz==(long)BB*NGG)    gtl=(const int*)d_in[i];
    }
    const int smem = 2*TILE*CC*4;   // 165888 B
    cudaFuncSetAttribute(k_main, cudaFuncAttributeMaxDynamicSharedMemorySize, smem);
    k_init<<<512,256>>>();
    k_iou<<<dim3(NAA/1024, BB), 256>>>(anc, gtb);
    k_force<<<1, BB*NGG>>>();
    k_main<<<256, 256, smem>>>(cls, box, anc, gtb, gtl);
    k_select<<<64, 1024>>>();
    k_final<<<1, 32>>>((float*)d_out);
}